// round 16
// baseline (speedup 1.0000x reference)
#include <cuda_runtime.h>
#include <cuda_bf16.h>
#include <math.h>
#include <stdint.h>

// Problem constants
#define B_  4
#define T_  2048
#define C_  1024
#define H_  16
#define HD_ 64
#define M_  (B_*T_)          // 8192 rows

// Scratch (static device globals -- allocation-free per harness rules)
__device__ __nv_bfloat16 g_qkvh[(size_t)M_ * 3 * C_];   // bf16 hi q|k|v
__device__ __nv_bfloat16 g_qkvl[(size_t)M_ * 3 * C_];   // bf16 lo
__device__ __nv_bfloat16 g_xh[(size_t)M_ * C_], g_xl[(size_t)M_ * C_];
__device__ __nv_bfloat16 g_wah[(size_t)3 * C_ * C_], g_wal[(size_t)3 * C_ * C_];
__device__ __nv_bfloat16 g_wph[(size_t)C_ * C_],     g_wpl[(size_t)C_ * C_];
__device__ __nv_bfloat16 g_yh[(size_t)M_ * C_],      g_yl[(size_t)M_ * C_];

// ---------------------------------------------------------------------------
// helpers
// ---------------------------------------------------------------------------
__device__ __forceinline__ uint32_t smem_u32(const void* p) {
    uint32_t a;
    asm("{ .reg .u64 t; cvta.to.shared.u64 t, %1; cvt.u32.u64 %0, t; }"
        : "=r"(a) : "l"(p));
    return a;
}
__device__ __forceinline__ void cp16(uint32_t dst, const void* src) {
    asm volatile("cp.async.cg.shared.global [%0], [%1], 16;" :: "r"(dst), "l"(src));
}
__device__ __forceinline__ void cp_commit() {
    asm volatile("cp.async.commit_group;" ::: "memory");
}
template<int N> __device__ __forceinline__ void cp_wait() {
    asm volatile("cp.async.wait_group %0;" :: "n"(N) : "memory");
}

__device__ __forceinline__ void ldsm_x4(uint32_t* r, uint32_t addr) {
    asm volatile("ldmatrix.sync.aligned.m8n8.x4.shared.b16 {%0,%1,%2,%3}, [%4];"
                 : "=r"(r[0]), "=r"(r[1]), "=r"(r[2]), "=r"(r[3]) : "r"(addr));
}
__device__ __forceinline__ void ldsm_x4_t(uint32_t* r, uint32_t addr) {
    asm volatile("ldmatrix.sync.aligned.m8n8.x4.trans.shared.b16 {%0,%1,%2,%3}, [%4];"
                 : "=r"(r[0]), "=r"(r[1]), "=r"(r[2]), "=r"(r[3]) : "r"(addr));
}
__device__ __forceinline__ void mma16816b(float* d, const uint32_t* a,
                                          uint32_t b0, uint32_t b1) {
    asm volatile(
        "mma.sync.aligned.m16n8k16.row.col.f32.bf16.bf16.f32 "
        "{%0,%1,%2,%3}, {%4,%5,%6,%7}, {%8,%9}, {%0,%1,%2,%3};"
        : "+f"(d[0]), "+f"(d[1]), "+f"(d[2]), "+f"(d[3])
        : "r"(a[0]), "r"(a[1]), "r"(a[2]), "r"(a[3]), "r"(b0), "r"(b1));
}

// split fp32 pair into bf16 hi pair + bf16 lo pair (x -> low half, y -> high)
__device__ __forceinline__ void split2(float x, float y, uint32_t& hi, uint32_t& lo) {
    __nv_bfloat16 hx = __float2bfloat16(x);
    __nv_bfloat16 hy = __float2bfloat16(y);
    float fx = __bfloat162float(hx), fy = __bfloat162float(hy);
    __nv_bfloat16 lx = __float2bfloat16(x - fx);
    __nv_bfloat16 ly = __float2bfloat16(y - fy);
    uint16_t uhx = *(uint16_t*)&hx, uhy = *(uint16_t*)&hy;
    uint16_t ulx = *(uint16_t*)&lx, uly = *(uint16_t*)&ly;
    hi = ((uint32_t)uhy << 16) | uhx;
    lo = ((uint32_t)uly << 16) | ulx;
}

// ---------------------------------------------------------------------------
// generic fp32 -> bf16 hi/lo split (n4 float4 elements)
// ---------------------------------------------------------------------------
__global__ void __launch_bounds__(256) split_kernel(
    const float* __restrict__ in,
    __nv_bfloat16* __restrict__ oh, __nv_bfloat16* __restrict__ ol, int n4)
{
    int i = blockIdx.x * blockDim.x + threadIdx.x;
    if (i >= n4) return;
    float4 v = ((const float4*)in)[i];
    uint32_t h01, l01, h23, l23;
    split2(v.x, v.y, h01, l01);
    split2(v.z, v.w, h23, l23);
    *(uint2*)(oh + (size_t)i * 4) = make_uint2(h01, h23);
    *(uint2*)(ol + (size_t)i * 4) = make_uint2(l01, l23);
}

// ---------------------------------------------------------------------------
// bf16x3 warp-MMA GEMM, CTA tile 128x256, warp tile 64x64 (2x4 warps), occ 1.
// Rationale: 0.167 ldsm per MMA (vs 0.25 at 64x32) -- the smem crossbar was
// the binding resource at the old shape. cp.async 3-slot ring, 1 sync/K-blk,
// term-major MMA order.
// Stage (48KB): Ahi 8K | Alo 8K | Bhi 16K | Blo 16K.
// ---------------------------------------------------------------------------
#define GSTG 49152

__global__ void __launch_bounds__(256, 1) mma_gemm_bf16_nt(
    const __nv_bfloat16* __restrict__ Ah, const __nv_bfloat16* __restrict__ Al,
    const __nv_bfloat16* __restrict__ Bh, const __nv_bfloat16* __restrict__ Bl,
    float* __restrict__ C,
    __nv_bfloat16* __restrict__ Ch, __nv_bfloat16* __restrict__ Cl,
    int N, int K)
{
    extern __shared__ char smc[];
    const uint32_t smb = smem_u32(smc);
    const int tid  = threadIdx.x;
    const int lane = tid & 31;
    const int wid  = tid >> 5;
    const int m0w  = (wid >> 2) * 64;    // 0 or 64
    const int n0w  = (wid & 3) * 64;     // 0,64,128,192
    const int NKB  = K >> 5;

    const size_t brow = (size_t)blockIdx.y * 128;
    const size_t bcol = (size_t)blockIdx.x * 256;
    const __nv_bfloat16* Ahg = Ah + brow * K;
    const __nv_bfloat16* Alg = Al + brow * K;
    const __nv_bfloat16* Bhg = Bh + bcol * K;
    const __nv_bfloat16* Blg = Bl + bcol * K;

    // stage loader: 3072 16B-chunks; 12 per thread.
    //   i 0-1: A-hi (512 chunks: 128 rows x 4), i 2-3: A-lo,
    //   i 4-7: B-hi (1024 chunks: 256 rows x 4), i 8-11: B-lo
    auto issue_stage = [&](int slot, int k0) {
        const uint32_t sb = smb + (uint32_t)slot * GSTG;
        #pragma unroll
        for (int i = 0; i < 12; i++) {
            const __nv_bfloat16* gp;
            uint32_t base;
            int idx;
            if (i < 4) {
                gp   = (i < 2) ? Ahg : Alg;
                base = (i < 2) ? 0u : 8192u;
                idx  = tid + (i & 1) * 256;          // 0..511
            } else {
                gp   = (i < 8) ? Bhg : Blg;
                base = (i < 8) ? 16384u : 32768u;
                idx  = tid + ((i - 4) & 3) * 256;    // 0..1023
            }
            int r = idx >> 2, c = idx & 3;
            uint32_t dst = sb + base
                         + (uint32_t)r * 64 + (uint32_t)((c ^ ((r >> 1) & 3)) << 4);
            cp16(dst, gp + (size_t)r * K + k0 + c * 8);
        }
        cp_commit();
    };

    float acc[4][8][4];
    #pragma unroll
    for (int mt = 0; mt < 4; mt++)
        #pragma unroll
        for (int nt = 0; nt < 8; nt++)
            #pragma unroll
            for (int q = 0; q < 4; q++) acc[mt][nt][q] = 0.0f;

    issue_stage(0, 0);
    issue_stage(1, 32);

    int slot = 0;
    for (int kb = 0; kb < NKB; kb++) {
        if (kb + 1 < NKB) cp_wait<1>(); else cp_wait<0>();
        __syncthreads();
        if (kb + 2 < NKB) issue_stage((slot + 2) % 3, (kb + 2) << 5);

        const uint32_t base = smb + (uint32_t)slot * GSTG;
        #pragma unroll
        for (int ks = 0; ks < 2; ks++) {
            uint32_t Ahi[4][4], Alo[4][4];
            #pragma unroll
            for (int mt = 0; mt < 4; mt++) {
                int r  = m0w + mt * 16 + (lane & 15);
                int ch = 2 * ks + (lane >> 4);
                uint32_t off = (uint32_t)r * 64 + (uint32_t)((ch ^ ((r >> 1) & 3)) << 4);
                ldsm_x4(Ahi[mt], base + off);
                ldsm_x4(Alo[mt], base + 8192 + off);
            }
            #pragma unroll
            for (int np = 0; np < 4; np++) {
                int g  = lane >> 3;
                int r  = n0w + (2 * np + (g >> 1)) * 8 + (lane & 7);
                int ch = 2 * ks + (g & 1);
                uint32_t off = (uint32_t)r * 64 + (uint32_t)((ch ^ ((r >> 1) & 3)) << 4);
                uint32_t Bh4[4], Bl4[4];
                ldsm_x4(Bh4, base + 16384 + off);
                ldsm_x4(Bl4, base + 32768 + off);
                // term-major: 8 independent accumulators per pass
                #pragma unroll
                for (int mt = 0; mt < 4; mt++) {
                    mma16816b(acc[mt][2*np],   Ahi[mt], Bh4[0], Bh4[1]);
                    mma16816b(acc[mt][2*np+1], Ahi[mt], Bh4[2], Bh4[3]);
                }
                #pragma unroll
                for (int mt = 0; mt < 4; mt++) {
                    mma16816b(acc[mt][2*np],   Ahi[mt], Bl4[0], Bl4[1]);
                    mma16816b(acc[mt][2*np+1], Ahi[mt], Bl4[2], Bl4[3]);
                }
                #pragma unroll
                for (int mt = 0; mt < 4; mt++) {
                    mma16816b(acc[mt][2*np],   Alo[mt], Bh4[0], Bh4[1]);
                    mma16816b(acc[mt][2*np+1], Alo[mt], Bh4[2], Bh4[3]);
                }
            }
        }
        slot = (slot + 1) % 3;
    }

    #pragma unroll
    for (int mt = 0; mt < 4; mt++) {
        int row0 = m0w + mt * 16 + (lane >> 2);
        #pragma unroll
        for (int nt = 0; nt < 8; nt++) {
            int col = n0w + nt * 8 + (lane & 3) * 2;
            size_t p0 = (brow + row0) * N + bcol + col;
            if (Ch) {
                uint32_t h0, l0, h1, l1;
                split2(acc[mt][nt][0], acc[mt][nt][1], h0, l0);
                split2(acc[mt][nt][2], acc[mt][nt][3], h1, l1);
                *(uint32_t*)(Ch + p0) = h0;
                *(uint32_t*)(Cl + p0) = l0;
                *(uint32_t*)(Ch + p0 + 8 * (size_t)N) = h1;
                *(uint32_t*)(Cl + p0 + 8 * (size_t)N) = l1;
            } else {
                *(float2*)(C + p0) = make_float2(acc[mt][nt][0], acc[mt][nt][1]);
                *(float2*)(C + p0 + 8 * (size_t)N) =
                    make_float2(acc[mt][nt][2], acc[mt][nt][3]);
            }
        }
    }
}

// ---------------------------------------------------------------------------
// RMSNorm + RoPE on q,k heads, reading and rewriting bf16 hi/lo in place.
// ---------------------------------------------------------------------------
__global__ void __launch_bounds__(256) rmsrope_split_kernel(
    __nv_bfloat16* __restrict__ qh, __nv_bfloat16* __restrict__ ql)
{
    int gv   = (blockIdx.x * blockDim.x + threadIdx.x) >> 5;
    int lane = threadIdx.x & 31;
    int which = gv & 1;
    int h     = (gv >> 1) & 15;
    int m     = gv >> 5;
    int t     = m & (T_ - 1);

    size_t off = (size_t)m * (3 * C_) + which * C_ + h * HD_;
    float x1 = __bfloat162float(qh[off + lane])      + __bfloat162float(ql[off + lane]);
    float x2 = __bfloat162float(qh[off + lane + 32]) + __bfloat162float(ql[off + lane + 32]);

    float ss = x1 * x1 + x2 * x2;
    #pragma unroll
    for (int o = 16; o; o >>= 1)
        ss += __shfl_xor_sync(0xffffffffu, ss, o);
    float r = rsqrtf(ss * (1.0f / 64.0f) + 1.1920929e-07f);
    x1 *= r; x2 *= r;

    float inv_f = powf(10000.0f, -(float)lane * (1.0f / 32.0f));
    float ang   = (float)t * inv_f;
    float cf, sf;
    sincosf(ang, &sf, &cf);
    float c = __bfloat162float(__float2bfloat16(cf));
    float s = __bfloat162float(__float2bfloat16(sf));

    float y1 =  x1 * c + x2 * s;
    float y2 = -x1 * s + x2 * c;

    __nv_bfloat16 h1 = __float2bfloat16(y1);
    __nv_bfloat16 h2 = __float2bfloat16(y2);
    qh[off + lane]      = h1;
    qh[off + lane + 32] = h2;
    ql[off + lane]      = __float2bfloat16(y1 - __bfloat162float(h1));
    ql[off + lane + 32] = __float2bfloat16(y2 - __bfloat162float(h2));
}

// ---------------------------------------------------------------------------
// Flash attention, bf16x3 warp MMA, fixed-max softmax, 2-slot KV ring,
// TWO CTAs PER SM. (Unchanged from R15 -- protect the win.)
// Smem: Q 32K | KV slot0..1 32K each (98304 B).
// ---------------------------------------------------------------------------
#define FQ_HI 0
#define FQ_LO 16384
#define FKV0  32768

__global__ void __launch_bounds__(256, 2) flash_mma_kernel(
    const __nv_bfloat16* __restrict__ qh, const __nv_bfloat16* __restrict__ ql,
    __nv_bfloat16* __restrict__ yh, __nv_bfloat16* __restrict__ yl)
{
    extern __shared__ char smc[];
    const uint32_t smb = smem_u32(smc);
    const int tid  = threadIdx.x;
    const int lane = tid & 31;
    const int wid  = tid >> 5;
    const int qblk = (gridDim.x - 1) - blockIdx.x;   // heaviest CTAs first
    const int bh   = blockIdx.y;
    const int b    = bh >> 4, h = bh & 15;
    const int q0   = qblk * 128;

    const size_t hb = (size_t)b * T_ * (3 * C_) + h * HD_;

    auto issue_kv = [&](int slot, int k0) {
        const uint32_t sb = smb + FKV0 + (uint32_t)slot * 32768;
        #pragma unroll
        for (int i = 0; i < 8; i++) {
            int idx = tid + (i & 1) * 256;
            int r = idx >> 3, c = idx & 7;
            size_t go = hb + (size_t)(k0 + r) * (3 * C_) + c * 8;
            const __nv_bfloat16* gp =
                (i < 2) ? (qh + go + C_)     : (i < 4) ? (ql + go + C_)
              : (i < 6) ? (qh + go + 2 * C_) : (ql + go + 2 * C_);
            uint32_t dst = sb + (uint32_t)(i >> 1) * 8192
                         + (uint32_t)r * 128 + (uint32_t)((c ^ (r & 7)) << 4);
            cp16(dst, gp);
        }
        cp_commit();
    };

    const int ktiles = 2 * qblk + 2;

    issue_kv(0, 0);
    #pragma unroll
    for (int i = 0; i < 4; i++) {
        int t = tid + i * 256;
        int r = t >> 3, c = t & 7;
        size_t go = hb + (size_t)(q0 + r) * (3 * C_) + c * 8;
        uint4 hv = *(const uint4*)(qh + go);
        uint4 lv = *(const uint4*)(ql + go);
        uint32_t off = r * 128 + ((c ^ (r & 7)) << 4);
        *(uint4*)(smc + FQ_HI + off) = hv;
        *(uint4*)(smc + FQ_LO + off) = lv;
    }

    float S[8][4], O[8][4];
    float rsum[2] = {0.f, 0.f};
    #pragma unroll
    for (int j = 0; j < 8; j++)
        #pragma unroll
        for (int q = 0; q < 4; q++) O[j][q] = 0.f;

    const int row0 = q0 + wid * 16 + (lane >> 2);

    for (int kt = 0; kt < ktiles; kt++) {
        const int k0 = kt * 64;
        cp_wait<0>();
        __syncthreads();
        if (kt + 1 < ktiles) issue_kv((kt + 1) & 1, (kt + 1) * 64);

        const uint32_t kvb = smb + FKV0 + (uint32_t)(kt & 1) * 32768;

        #pragma unroll
        for (int j = 0; j < 8; j++)
            #pragma unroll
            for (int q = 0; q < 4; q++) S[j][q] = 0.f;

        #pragma unroll
        for (int s = 0; s < 4; s++) {
            uint32_t Qh[4], Ql_[4];
            {
                int r  = wid * 16 + (lane & 15);
                int ch = 2 * s + (lane >> 4);
                uint32_t off = r * 128 + ((ch ^ (r & 7)) << 4);
                ldsm_x4(Qh,  smb + FQ_HI + off);
                ldsm_x4(Ql_, smb + FQ_LO + off);
            }
            uint32_t Kh[4][4], Kl[4][4];
            #pragma unroll
            for (int jp = 0; jp < 4; jp++) {
                int r  = jp * 16 + (lane & 15);
                int ch = 2 * s + (lane >> 4);
                uint32_t off = r * 128 + ((ch ^ (r & 7)) << 4);
                ldsm_x4(Kh[jp], kvb + off);
                ldsm_x4(Kl[jp], kvb + 8192 + off);
            }
            #pragma unroll
            for (int jp = 0; jp < 4; jp++) {
                mma16816b(S[2*jp],   Qh, Kh[jp][0], Kh[jp][2]);
                mma16816b(S[2*jp+1], Qh, Kh[jp][1], Kh[jp][3]);
            }
            #pragma unroll
            for (int jp = 0; jp < 4; jp++) {
                mma16816b(S[2*jp],   Ql_, Kh[jp][0], Kh[jp][2]);
                mma16816b(S[2*jp+1], Ql_, Kh[jp][1], Kh[jp][3]);
            }
            #pragma unroll
            for (int jp = 0; jp < 4; jp++) {
                mma16816b(S[2*jp],   Qh, Kl[jp][0], Kl[jp][2]);
                mma16816b(S[2*jp+1], Qh, Kl[jp][1], Kl[jp][3]);
            }
        }

        if (kt >= 2 * qblk) {
            #pragma unroll
            for (int j = 0; j < 8; j++) {
                int colb = k0 + j * 8 + (lane & 3) * 2;
                #pragma unroll
                for (int q = 0; q < 4; q++) {
                    int key  = colb + (q & 1);
                    int grow = row0 + (q >> 1) * 8;
                    S[j][q] = (key > grow)
                            ? 0.f : __expf(fmaf(S[j][q], 0.125f, -8.f));
                }
            }
        } else {
            #pragma unroll
            for (int j = 0; j < 8; j++)
                #pragma unroll
                for (int q = 0; q < 4; q++)
                    S[j][q] = __expf(fmaf(S[j][q], 0.125f, -8.f));
        }

        #pragma unroll
        for (int hf = 0; hf < 2; hf++) {
            float ps = 0.f;
            #pragma unroll
            for (int j = 0; j < 8; j++)
                ps += S[j][2*hf] + S[j][2*hf+1];
            ps += __shfl_xor_sync(0xffffffffu, ps, 1);
            ps += __shfl_xor_sync(0xffffffffu, ps, 2);
            rsum[hf] += ps;
        }

        #pragma unroll
        for (int s = 0; s < 4; s++) {
            uint32_t Ph[4], Pl[4];
            split2(S[2*s][0],   S[2*s][1],   Ph[0], Pl[0]);
            split2(S[2*s][2],   S[2*s][3],   Ph[1], Pl[1]);
            split2(S[2*s+1][0], S[2*s+1][1], Ph[2], Pl[2]);
            split2(S[2*s+1][2], S[2*s+1][3], Ph[3], Pl[3]);
            uint32_t Vh[4][4], Vl[4][4];
            #pragma unroll
            for (int jp = 0; jp < 4; jp++) {
                int mm = lane >> 3, lr = lane & 7;
                int r  = 16 * s + lr + 8 * (mm & 1);
                int ch = 2 * jp + (mm >> 1);
                uint32_t off = r * 128 + ((ch ^ (r & 7)) << 4);
                ldsm_x4_t(Vh[jp], kvb + 16384 + off);
                ldsm_x4_t(Vl[jp], kvb + 24576 + off);
            }
            #pragma unroll
            for (int jp = 0; jp < 4; jp++) {
                mma16816b(O[2*jp],   Ph, Vh[jp][0], Vh[jp][1]);
                mma16816b(O[2*jp+1], Ph, Vh[jp][2], Vh[jp][3]);
            }
            #pragma unroll
            for (int jp = 0; jp < 4; jp++) {
                mma16816b(O[2*jp],   Pl, Vh[jp][0], Vh[jp][1]);
                mma16816b(O[2*jp+1], Pl, Vh[jp][2], Vh[jp][3]);
            }
            #pragma unroll
            for (int jp = 0; jp < 4; jp++) {
                mma16816b(O[2*jp],   Ph, Vl[jp][0], Vl[jp][1]);
                mma16816b(O[2*jp+1], Ph, Vl[jp][2], Vl[jp][3]);
            }
        }
    }

    float inv0 = 1.f / rsum[0], inv1 = 1.f / rsum[1];
    #pragma unroll
    for (int j = 0; j < 8; j++) {
        int col = h * HD_ + j * 8 + (lane & 3) * 2;
        size_t base0 = ((size_t)b * T_ + row0) * C_ + col;
        uint32_t h01, l01, h23, l23;
        split2(O[j][0] * inv0, O[j][1] * inv0, h01, l01);
        split2(O[j][2] * inv1, O[j][3] * inv1, h23, l23);
        *(uint32_t*)(yh + base0) = h01;
        *(uint32_t*)(yl + base0) = l01;
        *(uint32_t*)(yh + base0 + 8 * (size_t)C_) = h23;
        *(uint32_t*)(yl + base0 + 8 * (size_t)C_) = l23;
    }
}

// ---------------------------------------------------------------------------
// Launch
// ---------------------------------------------------------------------------
extern "C" void kernel_launch(void* const* d_in, const int* in_sizes, int n_in,
                              void* d_out, int out_size)
{
    const float* x      = (const float*)d_in[0];
    const float* w_attn = (const float*)d_in[1];
    const float* w_proj = (const float*)d_in[2];
    float* out = (float*)d_out;

    __nv_bfloat16 *qkvh, *qkvl, *xh, *xl, *wah, *wal, *wph, *wpl, *yh, *yl;
    cudaGetSymbolAddress((void**)&qkvh, g_qkvh);
    cudaGetSymbolAddress((void**)&qkvl, g_qkvl);
    cudaGetSymbolAddress((void**)&xh,   g_xh);
    cudaGetSymbolAddress((void**)&xl,   g_xl);
    cudaGetSymbolAddress((void**)&wah,  g_wah);
    cudaGetSymbolAddress((void**)&wal,  g_wal);
    cudaGetSymbolAddress((void**)&wph,  g_wph);
    cudaGetSymbolAddress((void**)&wpl,  g_wpl);
    cudaGetSymbolAddress((void**)&yh,   g_yh);
    cudaGetSymbolAddress((void**)&yl,   g_yl);

    const int gemm_smem  = 3 * GSTG;          // 147456
    const int flash_smem = 32768 + 2 * 32768; // 98304 (2 CTAs/SM)
    cudaFuncSetAttribute(mma_gemm_bf16_nt,
                         cudaFuncAttributeMaxDynamicSharedMemorySize, gemm_smem);
    cudaFuncSetAttribute(flash_mma_kernel,
                         cudaFuncAttributeMaxDynamicSharedMemorySize, flash_smem);

    // 0) split inputs to bf16 hi/lo
    split_kernel<<<(M_ * C_ / 4) / 256, 256>>>(x, xh, xl, M_ * C_ / 4);
    split_kernel<<<(3 * C_ * C_ / 4) / 256, 256>>>(w_attn, wah, wal, 3 * C_ * C_ / 4);
    split_kernel<<<(C_ * C_ / 4) / 256, 256>>>(w_proj, wph, wpl, C_ * C_ / 4);

    // 1) qkv = x @ w_attn^T  -> bf16 hi/lo directly
    {
        dim3 grid(3 * C_ / 256, M_ / 128);   // 12 x 64
        mma_gemm_bf16_nt<<<grid, 256, gemm_smem>>>(xh, xl, wah, wal,
                                                   nullptr, qkvh, qkvl,
                                                   3 * C_, C_);
    }

    // 2) RMSNorm + RoPE on q,k (in place on hi/lo)
    rmsrope_split_kernel<<<(2 * M_ * H_) / 8, 256>>>(qkvh, qkvl);

    // 3) Flash attention -> yh/yl  (largest-first, fixed-max softmax, occ 2)
    {
        dim3 grid(T_ / 128, B_ * H_);
        flash_mma_kernel<<<grid, 256, flash_smem>>>(qkvh, qkvl, yh, yl);
    }

    // 4) out = y @ w_proj^T  (fp32 out)
    {
        dim3 grid(C_ / 256, M_ / 128);       // 4 x 64
        mma_gemm_bf16_nt<<<grid, 256, gemm_smem>>>(yh, yl, wph, wpl,
                                                   out, nullptr, nullptr,
                                                   C_, C_);
    }
}

// round 17
// speedup vs baseline: 1.1171x; 1.1171x over previous
#include <cuda_runtime.h>
#include <cuda_bf16.h>
#include <math.h>
#include <stdint.h>

// Problem constants
#define B_  4
#define T_  2048
#define C_  1024
#define H_  16
#define HD_ 64
#define M_  (B_*T_)          // 8192 rows

// Scratch (static device globals -- allocation-free per harness rules)
__device__ __nv_bfloat16 g_qkvh[(size_t)M_ * 3 * C_];   // bf16 hi q|k|v
__device__ __nv_bfloat16 g_qkvl[(size_t)M_ * 3 * C_];   // bf16 lo
__device__ __nv_bfloat16 g_xh[(size_t)M_ * C_], g_xl[(size_t)M_ * C_];
__device__ __nv_bfloat16 g_wah[(size_t)3 * C_ * C_], g_wal[(size_t)3 * C_ * C_];
__device__ __nv_bfloat16 g_wph[(size_t)C_ * C_],     g_wpl[(size_t)C_ * C_];
__device__ __nv_bfloat16 g_yh[(size_t)M_ * C_],      g_yl[(size_t)M_ * C_];
__device__ uint32_t g_cs[T_ * 32];                      // packed bf16 (cos,sin)

// ---------------------------------------------------------------------------
// helpers
// ---------------------------------------------------------------------------
__device__ __forceinline__ uint32_t smem_u32(const void* p) {
    uint32_t a;
    asm("{ .reg .u64 t; cvta.to.shared.u64 t, %1; cvt.u32.u64 %0, t; }"
        : "=r"(a) : "l"(p));
    return a;
}
__device__ __forceinline__ void cp16(uint32_t dst, const void* src) {
    asm volatile("cp.async.cg.shared.global [%0], [%1], 16;" :: "r"(dst), "l"(src));
}
__device__ __forceinline__ void cp_commit() {
    asm volatile("cp.async.commit_group;" ::: "memory");
}
template<int N> __device__ __forceinline__ void cp_wait() {
    asm volatile("cp.async.wait_group %0;" :: "n"(N) : "memory");
}

__device__ __forceinline__ void ldsm_x4(uint32_t* r, uint32_t addr) {
    asm volatile("ldmatrix.sync.aligned.m8n8.x4.shared.b16 {%0,%1,%2,%3}, [%4];"
                 : "=r"(r[0]), "=r"(r[1]), "=r"(r[2]), "=r"(r[3]) : "r"(addr));
}
__device__ __forceinline__ void ldsm_x4_t(uint32_t* r, uint32_t addr) {
    asm volatile("ldmatrix.sync.aligned.m8n8.x4.trans.shared.b16 {%0,%1,%2,%3}, [%4];"
                 : "=r"(r[0]), "=r"(r[1]), "=r"(r[2]), "=r"(r[3]) : "r"(addr));
}
__device__ __forceinline__ void mma16816b(float* d, const uint32_t* a,
                                          uint32_t b0, uint32_t b1) {
    asm volatile(
        "mma.sync.aligned.m16n8k16.row.col.f32.bf16.bf16.f32 "
        "{%0,%1,%2,%3}, {%4,%5,%6,%7}, {%8,%9}, {%0,%1,%2,%3};"
        : "+f"(d[0]), "+f"(d[1]), "+f"(d[2]), "+f"(d[3])
        : "r"(a[0]), "r"(a[1]), "r"(a[2]), "r"(a[3]), "r"(b0), "r"(b1));
}

// split fp32 pair into bf16 hi pair + bf16 lo pair (x -> low half, y -> high)
__device__ __forceinline__ void split2(float x, float y, uint32_t& hi, uint32_t& lo) {
    __nv_bfloat16 hx = __float2bfloat16(x);
    __nv_bfloat16 hy = __float2bfloat16(y);
    float fx = __bfloat162float(hx), fy = __bfloat162float(hy);
    __nv_bfloat16 lx = __float2bfloat16(x - fx);
    __nv_bfloat16 ly = __float2bfloat16(y - fy);
    uint16_t uhx = *(uint16_t*)&hx, uhy = *(uint16_t*)&hy;
    uint16_t ulx = *(uint16_t*)&lx, uly = *(uint16_t*)&ly;
    hi = ((uint32_t)uhy << 16) | uhx;
    lo = ((uint32_t)uly << 16) | ulx;
}

// ---------------------------------------------------------------------------
// generic fp32 -> bf16 hi/lo split (n4 float4 elements)
// ---------------------------------------------------------------------------
__global__ void __launch_bounds__(256) split_kernel(
    const float* __restrict__ in,
    __nv_bfloat16* __restrict__ oh, __nv_bfloat16* __restrict__ ol, int n4)
{
    int i = blockIdx.x * blockDim.x + threadIdx.x;
    if (i >= n4) return;
    float4 v = ((const float4*)in)[i];
    uint32_t h01, l01, h23, l23;
    split2(v.x, v.y, h01, l01);
    split2(v.z, v.w, h23, l23);
    *(uint2*)(oh + (size_t)i * 4) = make_uint2(h01, h23);
    *(uint2*)(ol + (size_t)i * 4) = make_uint2(l01, l23);
}

// ---------------------------------------------------------------------------
// RoPE cos/sin table: bf16-rounded, packed (cos lo16, sin hi16).
// One entry per (t, freq-lane): 2048 x 32.
// ---------------------------------------------------------------------------
__global__ void __launch_bounds__(256) cs_table_kernel(uint32_t* __restrict__ cs)
{
    int idx  = blockIdx.x * blockDim.x + threadIdx.x;   // t*32 + lane
    int lane = idx & 31;
    int t    = idx >> 5;
    float inv_f = powf(10000.0f, -(float)lane * (1.0f / 32.0f));
    float ang   = (float)t * inv_f;
    float cf, sf;
    sincosf(ang, &sf, &cf);
    __nv_bfloat16 c = __float2bfloat16(cf);
    __nv_bfloat16 s = __float2bfloat16(sf);
    cs[idx] = ((uint32_t)(*(uint16_t*)&s) << 16) | (*(uint16_t*)&c);
}

// ---------------------------------------------------------------------------
// bf16x3 warp-MMA GEMM, 128x128 CTA, occ 2, cp.async 3-slot ring, 1 sync/K-blk,
// TERM-MAJOR MMA order. (R14 configuration -- the proven 402us.)
// ---------------------------------------------------------------------------
#define GSTG 32768

__global__ void __launch_bounds__(256, 2) mma_gemm_bf16_nt(
    const __nv_bfloat16* __restrict__ Ah, const __nv_bfloat16* __restrict__ Al,
    const __nv_bfloat16* __restrict__ Bh, const __nv_bfloat16* __restrict__ Bl,
    float* __restrict__ C,
    __nv_bfloat16* __restrict__ Ch, __nv_bfloat16* __restrict__ Cl,
    int N, int K)
{
    extern __shared__ char smc[];
    const uint32_t smb = smem_u32(smc);
    const int tid  = threadIdx.x;
    const int lane = tid & 31;
    const int wid  = tid >> 5;
    const int m0w  = (wid >> 2) * 64;
    const int n0w  = (wid & 3) * 32;
    const int NKB  = K >> 5;

    const size_t brow = (size_t)blockIdx.y * 128;
    const size_t bcol = (size_t)blockIdx.x * 128;
    const __nv_bfloat16* Ahg = Ah + brow * K;
    const __nv_bfloat16* Alg = Al + brow * K;
    const __nv_bfloat16* Bhg = Bh + bcol * K;
    const __nv_bfloat16* Blg = Bl + bcol * K;

    auto issue_stage = [&](int slot, int k0) {
        const uint32_t sb = smb + (uint32_t)slot * GSTG;
        #pragma unroll
        for (int i = 0; i < 8; i++) {
            const __nv_bfloat16* gp = (i < 2) ? Ahg : (i < 4) ? Alg
                                    : (i < 6) ? Bhg : Blg;
            int idx = tid + (i & 1) * 256;
            int r = idx >> 2, c = idx & 3;
            uint32_t dst = sb + (uint32_t)(i >> 1) * 8192
                         + (uint32_t)r * 64 + (uint32_t)((c ^ ((r >> 1) & 3)) << 4);
            cp16(dst, gp + (size_t)r * K + k0 + c * 8);
        }
        cp_commit();
    };

    float acc[4][4][4];
    #pragma unroll
    for (int mt = 0; mt < 4; mt++)
        #pragma unroll
        for (int nt = 0; nt < 4; nt++)
            #pragma unroll
            for (int q = 0; q < 4; q++) acc[mt][nt][q] = 0.0f;

    issue_stage(0, 0);
    issue_stage(1, 32);

    int slot = 0;
    for (int kb = 0; kb < NKB; kb++) {
        if (kb + 1 < NKB) cp_wait<1>(); else cp_wait<0>();
        __syncthreads();
        if (kb + 2 < NKB) issue_stage((slot + 2) % 3, (kb + 2) << 5);

        const uint32_t base = smb + (uint32_t)slot * GSTG;
        #pragma unroll
        for (int ks = 0; ks < 2; ks++) {
            uint32_t Ahi[4][4], Alo[4][4];
            #pragma unroll
            for (int mt = 0; mt < 4; mt++) {
                int r  = m0w + mt * 16 + (lane & 15);
                int ch = 2 * ks + (lane >> 4);
                uint32_t off = (uint32_t)r * 64 + (uint32_t)((ch ^ ((r >> 1) & 3)) << 4);
                ldsm_x4(Ahi[mt], base + off);
                ldsm_x4(Alo[mt], base + 8192 + off);
            }
            uint32_t Bh4[2][4], Bl4[2][4];
            #pragma unroll
            for (int np = 0; np < 2; np++) {
                int g  = lane >> 3;
                int r  = n0w + (2 * np + (g >> 1)) * 8 + (lane & 7);
                int ch = 2 * ks + (g & 1);
                uint32_t off = (uint32_t)r * 64 + (uint32_t)((ch ^ ((r >> 1) & 3)) << 4);
                ldsm_x4(Bh4[np], base + 16384 + off);
                ldsm_x4(Bl4[np], base + 24576 + off);
            }
            #pragma unroll
            for (int mt = 0; mt < 4; mt++) {
                mma16816b(acc[mt][0], Ahi[mt], Bh4[0][0], Bh4[0][1]);
                mma16816b(acc[mt][1], Ahi[mt], Bh4[0][2], Bh4[0][3]);
                mma16816b(acc[mt][2], Ahi[mt], Bh4[1][0], Bh4[1][1]);
                mma16816b(acc[mt][3], Ahi[mt], Bh4[1][2], Bh4[1][3]);
            }
            #pragma unroll
            for (int mt = 0; mt < 4; mt++) {
                mma16816b(acc[mt][0], Ahi[mt], Bl4[0][0], Bl4[0][1]);
                mma16816b(acc[mt][1], Ahi[mt], Bl4[0][2], Bl4[0][3]);
                mma16816b(acc[mt][2], Ahi[mt], Bl4[1][0], Bl4[1][1]);
                mma16816b(acc[mt][3], Ahi[mt], Bl4[1][2], Bl4[1][3]);
            }
            #pragma unroll
            for (int mt = 0; mt < 4; mt++) {
                mma16816b(acc[mt][0], Alo[mt], Bh4[0][0], Bh4[0][1]);
                mma16816b(acc[mt][1], Alo[mt], Bh4[0][2], Bh4[0][3]);
                mma16816b(acc[mt][2], Alo[mt], Bh4[1][0], Bh4[1][1]);
                mma16816b(acc[mt][3], Alo[mt], Bh4[1][2], Bh4[1][3]);
            }
        }
        slot = (slot + 1) % 3;
    }

    #pragma unroll
    for (int mt = 0; mt < 4; mt++) {
        int row0 = m0w + mt * 16 + (lane >> 2);
        #pragma unroll
        for (int nt = 0; nt < 4; nt++) {
            int col = n0w + nt * 8 + (lane & 3) * 2;
            size_t p0 = (brow + row0) * N + bcol + col;
            if (Ch) {
                uint32_t h0, l0, h1, l1;
                split2(acc[mt][nt][0], acc[mt][nt][1], h0, l0);
                split2(acc[mt][nt][2], acc[mt][nt][3], h1, l1);
                *(uint32_t*)(Ch + p0) = h0;
                *(uint32_t*)(Cl + p0) = l0;
                *(uint32_t*)(Ch + p0 + 8 * (size_t)N) = h1;
                *(uint32_t*)(Cl + p0 + 8 * (size_t)N) = l1;
            } else {
                *(float2*)(C + p0) = make_float2(acc[mt][nt][0], acc[mt][nt][1]);
                *(float2*)(C + p0 + 8 * (size_t)N) =
                    make_float2(acc[mt][nt][2], acc[mt][nt][3]);
            }
        }
    }
}

// ---------------------------------------------------------------------------
// RMSNorm + RoPE on q,k heads, bf16 hi/lo in place; cos/sin from table.
// ---------------------------------------------------------------------------
__global__ void __launch_bounds__(256) rmsrope_split_kernel(
    __nv_bfloat16* __restrict__ qh, __nv_bfloat16* __restrict__ ql,
    const uint32_t* __restrict__ cs)
{
    int gv   = (blockIdx.x * blockDim.x + threadIdx.x) >> 5;
    int lane = threadIdx.x & 31;
    int which = gv & 1;
    int h     = (gv >> 1) & 15;
    int m     = gv >> 5;
    int t     = m & (T_ - 1);

    size_t off = (size_t)m * (3 * C_) + which * C_ + h * HD_;
    float x1 = __bfloat162float(qh[off + lane])      + __bfloat162float(ql[off + lane]);
    float x2 = __bfloat162float(qh[off + lane + 32]) + __bfloat162float(ql[off + lane + 32]);

    float ss = x1 * x1 + x2 * x2;
    #pragma unroll
    for (int o = 16; o; o >>= 1)
        ss += __shfl_xor_sync(0xffffffffu, ss, o);
    float r = rsqrtf(ss * (1.0f / 64.0f) + 1.1920929e-07f);
    x1 *= r; x2 *= r;

    uint32_t p = cs[t * 32 + lane];
    uint16_t cu = (uint16_t)(p & 0xffff), su = (uint16_t)(p >> 16);
    float c = __bfloat162float(*(__nv_bfloat16*)&cu);
    float s = __bfloat162float(*(__nv_bfloat16*)&su);

    float y1 =  x1 * c + x2 * s;
    float y2 = -x1 * s + x2 * c;

    __nv_bfloat16 h1 = __float2bfloat16(y1);
    __nv_bfloat16 h2 = __float2bfloat16(y2);
    qh[off + lane]      = h1;
    qh[off + lane + 32] = h2;
    ql[off + lane]      = __float2bfloat16(y1 - __bfloat162float(h1));
    ql[off + lane + 32] = __float2bfloat16(y2 - __bfloat162float(h2));
}

// ---------------------------------------------------------------------------
// Flash attention, bf16x3 warp MMA, fixed-max softmax, 2-slot KV ring,
// TWO CTAs PER SM. (R15 configuration -- the proven winner.)
// Smem: Q 32K | KV slot0..1 32K each (98304 B).
// ---------------------------------------------------------------------------
#define FQ_HI 0
#define FQ_LO 16384
#define FKV0  32768

__global__ void __launch_bounds__(256, 2) flash_mma_kernel(
    const __nv_bfloat16* __restrict__ qh, const __nv_bfloat16* __restrict__ ql,
    __nv_bfloat16* __restrict__ yh, __nv_bfloat16* __restrict__ yl)
{
    extern __shared__ char smc[];
    const uint32_t smb = smem_u32(smc);
    const int tid  = threadIdx.x;
    const int lane = tid & 31;
    const int wid  = tid >> 5;
    const int qblk = (gridDim.x - 1) - blockIdx.x;   // heaviest CTAs first
    const int bh   = blockIdx.y;
    const int b    = bh >> 4, h = bh & 15;
    const int q0   = qblk * 128;

    const size_t hb = (size_t)b * T_ * (3 * C_) + h * HD_;

    auto issue_kv = [&](int slot, int k0) {
        const uint32_t sb = smb + FKV0 + (uint32_t)slot * 32768;
        #pragma unroll
        for (int i = 0; i < 8; i++) {
            int idx = tid + (i & 1) * 256;
            int r = idx >> 3, c = idx & 7;
            size_t go = hb + (size_t)(k0 + r) * (3 * C_) + c * 8;
            const __nv_bfloat16* gp =
                (i < 2) ? (qh + go + C_)     : (i < 4) ? (ql + go + C_)
              : (i < 6) ? (qh + go + 2 * C_) : (ql + go + 2 * C_);
            uint32_t dst = sb + (uint32_t)(i >> 1) * 8192
                         + (uint32_t)r * 128 + (uint32_t)((c ^ (r & 7)) << 4);
            cp16(dst, gp);
        }
        cp_commit();
    };

    const int ktiles = 2 * qblk + 2;

    issue_kv(0, 0);
    #pragma unroll
    for (int i = 0; i < 4; i++) {
        int t = tid + i * 256;
        int r = t >> 3, c = t & 7;
        size_t go = hb + (size_t)(q0 + r) * (3 * C_) + c * 8;
        uint4 hv = *(const uint4*)(qh + go);
        uint4 lv = *(const uint4*)(ql + go);
        uint32_t off = r * 128 + ((c ^ (r & 7)) << 4);
        *(uint4*)(smc + FQ_HI + off) = hv;
        *(uint4*)(smc + FQ_LO + off) = lv;
    }

    float S[8][4], O[8][4];
    float rsum[2] = {0.f, 0.f};
    #pragma unroll
    for (int j = 0; j < 8; j++)
        #pragma unroll
        for (int q = 0; q < 4; q++) O[j][q] = 0.f;

    const int row0 = q0 + wid * 16 + (lane >> 2);

    for (int kt = 0; kt < ktiles; kt++) {
        const int k0 = kt * 64;
        cp_wait<0>();
        __syncthreads();
        if (kt + 1 < ktiles) issue_kv((kt + 1) & 1, (kt + 1) * 64);

        const uint32_t kvb = smb + FKV0 + (uint32_t)(kt & 1) * 32768;

        #pragma unroll
        for (int j = 0; j < 8; j++)
            #pragma unroll
            for (int q = 0; q < 4; q++) S[j][q] = 0.f;

        #pragma unroll
        for (int s = 0; s < 4; s++) {
            uint32_t Qh[4], Ql_[4];
            {
                int r  = wid * 16 + (lane & 15);
                int ch = 2 * s + (lane >> 4);
                uint32_t off = r * 128 + ((ch ^ (r & 7)) << 4);
                ldsm_x4(Qh,  smb + FQ_HI + off);
                ldsm_x4(Ql_, smb + FQ_LO + off);
            }
            uint32_t Kh[4][4], Kl[4][4];
            #pragma unroll
            for (int jp = 0; jp < 4; jp++) {
                int r  = jp * 16 + (lane & 15);
                int ch = 2 * s + (lane >> 4);
                uint32_t off = r * 128 + ((ch ^ (r & 7)) << 4);
                ldsm_x4(Kh[jp], kvb + off);
                ldsm_x4(Kl[jp], kvb + 8192 + off);
            }
            #pragma unroll
            for (int jp = 0; jp < 4; jp++) {
                mma16816b(S[2*jp],   Qh, Kh[jp][0], Kh[jp][2]);
                mma16816b(S[2*jp+1], Qh, Kh[jp][1], Kh[jp][3]);
            }
            #pragma unroll
            for (int jp = 0; jp < 4; jp++) {
                mma16816b(S[2*jp],   Ql_, Kh[jp][0], Kh[jp][2]);
                mma16816b(S[2*jp+1], Ql_, Kh[jp][1], Kh[jp][3]);
            }
            #pragma unroll
            for (int jp = 0; jp < 4; jp++) {
                mma16816b(S[2*jp],   Qh, Kl[jp][0], Kl[jp][2]);
                mma16816b(S[2*jp+1], Qh, Kl[jp][1], Kl[jp][3]);
            }
        }

        if (kt >= 2 * qblk) {
            #pragma unroll
            for (int j = 0; j < 8; j++) {
                int colb = k0 + j * 8 + (lane & 3) * 2;
                #pragma unroll
                for (int q = 0; q < 4; q++) {
                    int key  = colb + (q & 1);
                    int grow = row0 + (q >> 1) * 8;
                    S[j][q] = (key > grow)
                            ? 0.f : __expf(fmaf(S[j][q], 0.125f, -8.f));
                }
            }
        } else {
            #pragma unroll
            for (int j = 0; j < 8; j++)
                #pragma unroll
                for (int q = 0; q < 4; q++)
                    S[j][q] = __expf(fmaf(S[j][q], 0.125f, -8.f));
        }

        #pragma unroll
        for (int hf = 0; hf < 2; hf++) {
            float ps = 0.f;
            #pragma unroll
            for (int j = 0; j < 8; j++)
                ps += S[j][2*hf] + S[j][2*hf+1];
            ps += __shfl_xor_sync(0xffffffffu, ps, 1);
            ps += __shfl_xor_sync(0xffffffffu, ps, 2);
            rsum[hf] += ps;
        }

        #pragma unroll
        for (int s = 0; s < 4; s++) {
            uint32_t Ph[4], Pl[4];
            split2(S[2*s][0],   S[2*s][1],   Ph[0], Pl[0]);
            split2(S[2*s][2],   S[2*s][3],   Ph[1], Pl[1]);
            split2(S[2*s+1][0], S[2*s+1][1], Ph[2], Pl[2]);
            split2(S[2*s+1][2], S[2*s+1][3], Ph[3], Pl[3]);
            uint32_t Vh[4][4], Vl[4][4];
            #pragma unroll
            for (int jp = 0; jp < 4; jp++) {
                int mm = lane >> 3, lr = lane & 7;
                int r  = 16 * s + lr + 8 * (mm & 1);
                int ch = 2 * jp + (mm >> 1);
                uint32_t off = r * 128 + ((ch ^ (r & 7)) << 4);
                ldsm_x4_t(Vh[jp], kvb + 16384 + off);
                ldsm_x4_t(Vl[jp], kvb + 24576 + off);
            }
            #pragma unroll
            for (int jp = 0; jp < 4; jp++) {
                mma16816b(O[2*jp],   Ph, Vh[jp][0], Vh[jp][1]);
                mma16816b(O[2*jp+1], Ph, Vh[jp][2], Vh[jp][3]);
            }
            #pragma unroll
            for (int jp = 0; jp < 4; jp++) {
                mma16816b(O[2*jp],   Pl, Vh[jp][0], Vh[jp][1]);
                mma16816b(O[2*jp+1], Pl, Vh[jp][2], Vh[jp][3]);
            }
            #pragma unroll
            for (int jp = 0; jp < 4; jp++) {
                mma16816b(O[2*jp],   Ph, Vl[jp][0], Vl[jp][1]);
                mma16816b(O[2*jp+1], Ph, Vl[jp][2], Vl[jp][3]);
            }
        }
    }

    float inv0 = 1.f / rsum[0], inv1 = 1.f / rsum[1];
    #pragma unroll
    for (int j = 0; j < 8; j++) {
        int col = h * HD_ + j * 8 + (lane & 3) * 2;
        size_t base0 = ((size_t)b * T_ + row0) * C_ + col;
        uint32_t h01, l01, h23, l23;
        split2(O[j][0] * inv0, O[j][1] * inv0, h01, l01);
        split2(O[j][2] * inv1, O[j][3] * inv1, h23, l23);
        *(uint32_t*)(yh + base0) = h01;
        *(uint32_t*)(yl + base0) = l01;
        *(uint32_t*)(yh + base0 + 8 * (size_t)C_) = h23;
        *(uint32_t*)(yl + base0 + 8 * (size_t)C_) = l23;
    }
}

// ---------------------------------------------------------------------------
// Launch
// ---------------------------------------------------------------------------
extern "C" void kernel_launch(void* const* d_in, const int* in_sizes, int n_in,
                              void* d_out, int out_size)
{
    const float* x      = (const float*)d_in[0];
    const float* w_attn = (const float*)d_in[1];
    const float* w_proj = (const float*)d_in[2];
    float* out = (float*)d_out;

    __nv_bfloat16 *qkvh, *qkvl, *xh, *xl, *wah, *wal, *wph, *wpl, *yh, *yl;
    uint32_t* cs;
    cudaGetSymbolAddress((void**)&qkvh, g_qkvh);
    cudaGetSymbolAddress((void**)&qkvl, g_qkvl);
    cudaGetSymbolAddress((void**)&xh,   g_xh);
    cudaGetSymbolAddress((void**)&xl,   g_xl);
    cudaGetSymbolAddress((void**)&wah,  g_wah);
    cudaGetSymbolAddress((void**)&wal,  g_wal);
    cudaGetSymbolAddress((void**)&wph,  g_wph);
    cudaGetSymbolAddress((void**)&wpl,  g_wpl);
    cudaGetSymbolAddress((void**)&yh,   g_yh);
    cudaGetSymbolAddress((void**)&yl,   g_yl);
    cudaGetSymbolAddress((void**)&cs,   g_cs);

    const int gemm_smem  = 3 * GSTG;          // 98304
    const int flash_smem = 32768 + 2 * 32768; // 98304 (2 CTAs/SM)
    cudaFuncSetAttribute(mma_gemm_bf16_nt,
                         cudaFuncAttributeMaxDynamicSharedMemorySize, gemm_smem);
    cudaFuncSetAttribute(flash_mma_kernel,
                         cudaFuncAttributeMaxDynamicSharedMemorySize, flash_smem);

    // 0) split inputs to bf16 hi/lo + RoPE cos/sin table
    split_kernel<<<(M_ * C_ / 4) / 256, 256>>>(x, xh, xl, M_ * C_ / 4);
    split_kernel<<<(3 * C_ * C_ / 4) / 256, 256>>>(w_attn, wah, wal, 3 * C_ * C_ / 4);
    split_kernel<<<(C_ * C_ / 4) / 256, 256>>>(w_proj, wph, wpl, C_ * C_ / 4);
    cs_table_kernel<<<(T_ * 32) / 256, 256>>>(cs);

    // 1) qkv = x @ w_attn^T  -> bf16 hi/lo directly
    {
        dim3 grid(3 * C_ / 128, M_ / 128);   // 24 x 64
        mma_gemm_bf16_nt<<<grid, 256, gemm_smem>>>(xh, xl, wah, wal,
                                                   nullptr, qkvh, qkvl,
                                                   3 * C_, C_);
    }

    // 2) RMSNorm + RoPE on q,k (in place on hi/lo, table-driven)
    rmsrope_split_kernel<<<(2 * M_ * H_) / 8, 256>>>(qkvh, qkvl, cs);

    // 3) Flash attention -> yh/yl  (largest-first, fixed-max softmax, occ 2)
    {
        dim3 grid(T_ / 128, B_ * H_);
        flash_mma_kernel<<<grid, 256, flash_smem>>>(qkvh, qkvl, yh, yl);
    }

    // 4) out = y @ w_proj^T  (fp32 out)
    {
        dim3 grid(C_ / 128, M_ / 128);       // 8 x 64
        mma_gemm_bf16_nt<<<grid, 256, gemm_smem>>>(yh, yl, wph, wpl,
                                                   out, nullptr, nullptr,
                                                   C_, C_);
    }
}